// round 13
// baseline (speedup 1.0000x reference)
#include <cuda_runtime.h>
#include <cuda_bf16.h>
#include <cstdint>

#define TOKENS 8192
#define INF    4096
#define OUTF   4096
#define RNK    16

// arch-specific (sm_103a) guard: tcgen05 only exists in the arch-specific pass.
#if defined(__CUDA_ARCH__) && (defined(__CUDA_ARCH_FEAT_SM103_ALL) || defined(__CUDA_ARCH_FEAT_SM100_ALL) || defined(__CUDA_ARCH_SPECIFIC__))
#define TC_PATH 1
#else
#define TC_PATH 0
#endif

// ===================== device scratch ==========================================
__device__ float g_KA[256];
__device__ float g_KB[256];
__device__ float g_C [256];
__device__ float g_T [TOKENS * RNK];
__device__ float g_D [OUTF   * RNK];
// bf16 hi/lo splits (4 bf16 packed per uint2)
__device__ uint2 g_xhi[(size_t)TOKENS * INF / 4];
__device__ uint2 g_xlo[(size_t)TOKENS * INF / 4];
__device__ uint2 g_whi[(size_t)OUTF   * INF / 4];
__device__ uint2 g_wlo[(size_t)OUTF   * INF / 4];

// ===================== portable PTX helpers ====================================
__device__ __forceinline__ uint32_t smem_to_u32(const void* p) {
    uint32_t a;
    asm("{ .reg .u64 t; cvta.to.shared.u64 t, %1; cvt.u32.u64 %0, t; }" : "=r"(a) : "l"(p));
    return a;
}
__device__ __forceinline__ uint32_t cluster_ctarank() {
    uint32_t r; asm("mov.u32 %0, %%cluster_ctarank;" : "=r"(r)); return r;
}
__device__ __forceinline__ uint32_t elect_one_pred() {
    uint32_t p;
    asm volatile("{\n\t.reg .pred p;\n\telect.sync _|p, 0xFFFFFFFF;\n\tselp.b32 %0, 1, 0, p;\n\t}" : "=r"(p));
    return p;
}

#define MBARRIER_INIT(addr, cnt) \
    asm volatile("mbarrier.init.shared.b64 [%0], %1;" :: "r"((uint32_t)(addr)), "r"((uint32_t)(cnt)) : "memory")

#define MBARRIER_ARRIVE_CLUSTER(addr, rank) \
    asm volatile("{\n\t.reg .b32 ra;\n\t" \
        "mapa.shared::cluster.u32 ra, %0, %1;\n\t" \
        "mbarrier.arrive.release.cluster.shared::cluster.b64 _, [ra];\n\t}" \
        :: "r"((uint32_t)(addr)), "r"((uint32_t)(rank)) : "memory")

#define MBARRIER_WAIT_PARITY(mbar, par) do { \
    uint32_t _m = (uint32_t)(mbar), _p = (uint32_t)(par), _d; \
    asm volatile("{\n\t.reg .pred p;\n\t" \
        "mbarrier.try_wait.parity.acquire.cta.shared::cta.b64 p, [%1], %2;\n\t" \
        "selp.b32 %0, 1, 0, p;\n\t}" : "=r"(_d) : "r"(_m), "r"(_p) : "memory"); \
    if (!_d) { \
        asm volatile("{\n\t.reg .pred P1;\n\t" \
            "WL_%=:\n\t" \
            "mbarrier.try_wait.parity.acquire.cta.shared::cta.b64 P1, [%0], %1, 0x989680;\n\t" \
            "@P1 bra.uni WD_%=;\n\t" \
            "bra.uni WL_%=;\n\t" \
            "WD_%=:\n\t}" :: "r"(_m), "r"(_p) : "memory"); \
    } \
} while (0)

#define MBARRIER_WAIT_PARITY_CLU(mbar, par) do { \
    uint32_t _m = (uint32_t)(mbar), _p = (uint32_t)(par), _d; \
    asm volatile("{\n\t.reg .pred p;\n\t" \
        "mbarrier.try_wait.parity.acquire.cluster.shared::cta.b64 p, [%1], %2;\n\t" \
        "selp.b32 %0, 1, 0, p;\n\t}" : "=r"(_d) : "r"(_m), "r"(_p) : "memory"); \
    if (!_d) { \
        asm volatile("{\n\t.reg .pred P1;\n\t" \
            "WLc_%=:\n\t" \
            "mbarrier.try_wait.parity.acquire.cluster.shared::cta.b64 P1, [%0], %1, 0x989680;\n\t" \
            "@P1 bra.uni WDc_%=;\n\t" \
            "bra.uni WLc_%=;\n\t" \
            "WDc_%=:\n\t}" :: "r"(_m), "r"(_p) : "memory"); \
    } \
} while (0)

#define CP_ASYNC16(dst, src) \
    asm volatile("cp.async.cg.shared.global [%0], [%1], 16;" :: "r"((uint32_t)(dst)), "l"(src) : "memory")
#define CP_ASYNC_COMMIT() asm volatile("cp.async.commit_group;" ::: "memory")
#define FENCE_PROXY_ASYNC() asm volatile("fence.proxy.async;" ::: "memory")
#define NAMED_BAR_PROD()    asm volatile("bar.sync 1, 256;" ::: "memory")
#define CLUSTER_SYNC() do { \
    asm volatile("barrier.cluster.arrive.aligned;" ::: "memory"); \
    asm volatile("barrier.cluster.wait.aligned;" ::: "memory"); \
} while (0)

// ===================== arch-specific tcgen05 helpers ===========================
#if TC_PATH
#define TCGEN05_ALLOC_CG2(sm, n) \
    asm volatile("tcgen05.alloc.cta_group::2.sync.aligned.shared::cta.b32 [%0], %1;" \
        :: "r"((uint32_t)(sm)), "r"((uint32_t)(n)) : "memory")
#define TCGEN05_DEALLOC_CG2(tm, n) \
    asm volatile("tcgen05.dealloc.cta_group::2.sync.aligned.b32 %0, %1;" :: "r"(tm), "r"((uint32_t)(n)))
#define TCGEN05_RELINQ_CG2() \
    asm volatile("tcgen05.relinquish_alloc_permit.cta_group::2.sync.aligned;")
#define TCGEN05_COMMIT_MC_CG2(mbar, mask) \
    asm volatile("tcgen05.commit.cta_group::2.mbarrier::arrive::one.shared::cluster.multicast::cluster.b64 [%0], %1;" \
        :: "r"((uint32_t)(mbar)), "h"((uint16_t)(mask)) : "memory")
#define TCGEN05_FENCE_AFTER()  asm volatile("tcgen05.fence::after_thread_sync;" ::: "memory")
#define TCGEN05_FENCE_BEFORE() asm volatile("tcgen05.fence::before_thread_sync;" ::: "memory")
#define TCGEN05_WAIT_LD()      asm volatile("tcgen05.wait::ld.sync.aligned;" ::: "memory")

#define TCGEN05_LD_32X32B_X32(r, a) \
    asm volatile("tcgen05.ld.sync.aligned.32x32b.x32.b32 " \
        "{%0, %1, %2, %3, %4, %5, %6, %7, %8, %9, %10, %11, %12, %13, %14, %15, " \
        "%16, %17, %18, %19, %20, %21, %22, %23, %24, %25, %26, %27, %28, %29, %30, %31}, [%32];" \
        : "=r"((r)[0]), "=r"((r)[1]), "=r"((r)[2]), "=r"((r)[3]), "=r"((r)[4]), "=r"((r)[5]), \
          "=r"((r)[6]), "=r"((r)[7]), "=r"((r)[8]), "=r"((r)[9]), "=r"((r)[10]), "=r"((r)[11]), \
          "=r"((r)[12]), "=r"((r)[13]), "=r"((r)[14]), "=r"((r)[15]), "=r"((r)[16]), "=r"((r)[17]), \
          "=r"((r)[18]), "=r"((r)[19]), "=r"((r)[20]), "=r"((r)[21]), "=r"((r)[22]), "=r"((r)[23]), \
          "=r"((r)[24]), "=r"((r)[25]), "=r"((r)[26]), "=r"((r)[27]), "=r"((r)[28]), "=r"((r)[29]), \
          "=r"((r)[30]), "=r"((r)[31]) : "r"(a))

__device__ __forceinline__ void mma_f16_ss_cg2(
    uint32_t d_tmem, uint64_t a_desc, uint64_t b_desc, uint32_t idesc, bool en_d)
{
    uint32_t en = en_d ? 1 : 0;
    asm volatile(
        "{\n\t.reg .pred p;\n\t"
        "setp.ne.u32 p, %6, 0;\n\t"
        "tcgen05.mma.cta_group::2.kind::f16 [%0], %1, %2, %3, "
        "{%4, %4, %4, %4, %4, %4, %4, %4}, p;\n\t}"
        :: "r"(d_tmem), "l"(a_desc), "l"(b_desc), "r"(idesc),
           "r"(0u), "r"(0u), "r"(en)
        : "memory");
}
#endif // TC_PATH

// K-major SW64 descriptor: layout=4, version=1, SBO=32 (512B = 8 rows x 64B), LBO=1
static constexpr uint64_t SMEM_DESC_BASE_SW64 =
    (uint64_t(4) << 61) | (uint64_t(1) << 46) | (uint64_t(32) << 32) | (uint64_t(1) << 16);
#define MAKE_SMEM_DESC64(a) (SMEM_DESC_BASE_SW64 | ((uint64_t)((a) >> 4) & 0x3FFF))

// ===================== kernel 0: f32 -> bf16 hi/lo split (once) =================
__global__ void conv_kernel(const float* __restrict__ x, const float* __restrict__ W) {
    const int64_t NX4 = (int64_t)TOKENS * INF / 4;
    const int64_t NW4 = (int64_t)OUTF   * INF / 4;
    const int64_t total = NX4 + NW4;
    int64_t stride = (int64_t)gridDim.x * blockDim.x;
    for (int64_t i = (int64_t)blockIdx.x * blockDim.x + threadIdx.x; i < total; i += stride) {
        float4 v = (i < NX4) ? ((const float4*)x)[i] : ((const float4*)W)[i - NX4];
        __nv_bfloat162 h0 = __floats2bfloat162_rn(v.x, v.y);
        __nv_bfloat162 h1 = __floats2bfloat162_rn(v.z, v.w);
        float2 f0 = __bfloat1622float2(h0);
        float2 f1 = __bfloat1622float2(h1);
        __nv_bfloat162 l0 = __floats2bfloat162_rn(v.x - f0.x, v.y - f0.y);
        __nv_bfloat162 l1 = __floats2bfloat162_rn(v.z - f1.x, v.w - f1.y);
        union U { __nv_bfloat162 b; unsigned u; };
        U ch0{h0}, ch1{h1}, cl0{l0}, cl1{l1};
        uint2 hv = make_uint2(ch0.u, ch1.u);
        uint2 lv = make_uint2(cl0.u, cl1.u);
        if (i < NX4) { g_xhi[i] = hv; g_xlo[i] = lv; }
        else         { g_whi[i - NX4] = hv; g_wlo[i - NX4] = lv; }
    }
}

// ===================== kernel 1: gram matrices ==================================
__global__ void gram_kernel(const float* __restrict__ A, const float* __restrict__ B) {
    __shared__ float red[256];
    int t = threadIdx.x, b = blockIdx.x;
    float s = 0.f;
    if (b < 256) {
        int i = b >> 4, j = b & 15;
        const float* ai = A + (size_t)i * INF;
        const float* aj = A + (size_t)j * INF;
        for (int k = t; k < INF; k += 256) s += ai[k] * aj[k];
    } else {
        int bb = b - 256;
        int i = bb >> 4, j = bb & 15;
        for (int k = t; k < OUTF; k += 256) s += B[(size_t)k * RNK + i] * B[(size_t)k * RNK + j];
    }
    red[t] = s; __syncthreads();
    for (int o = 128; o > 0; o >>= 1) { if (t < o) red[t] += red[t + o]; __syncthreads(); }
    if (t == 0) { if (b < 256) g_KA[b] = red[0]; else g_KB[b - 256] = red[0]; }
}

// ===================== kernel 2: Newton-Schulz (rank-16 subspace) ===============
__global__ void ns_kernel() {
    __shared__ float KA[256], KB[256], M[256], Y[256], Z[256], T1[256], T2[256];
    int t = threadIdx.x, i = t >> 4, j = t & 15;
    KA[t] = g_KA[t]; KB[t] = g_KB[t];
    __syncthreads();
    T1[t] = KA[t] * KB[t];
    __syncthreads();
    for (int o = 128; o > 0; o >>= 1) { if (t < o) T1[t] += T1[t + o]; __syncthreads(); }
    float alpha = sqrtf(T1[0]);
    __syncthreads();
    float s = alpha + 1e-7f;
    M[t] = (i == j) ? (1.0f / s) : 0.0f;
    __syncthreads();
    const float ca = 3.4445f, cb = -4.775f, cc = 2.0315f;
    #pragma unroll 1
    for (int it = 0; it < 5; it++) {
        float v = 0.f;
        #pragma unroll
        for (int q = 0; q < 16; q++) v += M[i*16+q] * KA[q*16+j];
        T1[t] = v; __syncthreads();
        v = 0.f;
        #pragma unroll
        for (int q = 0; q < 16; q++) v += T1[i*16+q] * M[j*16+q];
        Y[t] = v; __syncthreads();
        v = 0.f;
        #pragma unroll
        for (int q = 0; q < 16; q++) v += Y[i*16+q] * KB[q*16+j];
        T2[t] = v; __syncthreads();
        v = 0.f;
        #pragma unroll
        for (int q = 0; q < 16; q++) v += T2[i*16+q] * Y[q*16+j];
        Z[t] = v; __syncthreads();
        Y[t] = cb * Y[t] + cc * Z[t]; __syncthreads();
        v = 0.f;
        #pragma unroll
        for (int q = 0; q < 16; q++) v += Y[i*16+q] * KB[q*16+j];
        T2[t] = v; __syncthreads();
        v = ca * M[t];
        #pragma unroll
        for (int q = 0; q < 16; q++) v += T2[i*16+q] * M[q*16+j];
        T1[t] = v; __syncthreads();
        M[t] = T1[t]; __syncthreads();
    }
    g_C[t] = alpha * M[t];
}

// ===================== kernel 3: D = B @ (alpha*Mf) =============================
__global__ void dmat_kernel(const float* __restrict__ B) {
    __shared__ float C[256];
    int t = threadIdx.x;
    C[t] = g_C[t];
    __syncthreads();
    int jrow = blockIdx.x * 256 + t;
    float br[16];
    #pragma unroll
    for (int r4 = 0; r4 < 4; r4++) {
        float4 v = *(const float4*)(B + (size_t)jrow * RNK + r4 * 4);
        br[r4*4+0] = v.x; br[r4*4+1] = v.y; br[r4*4+2] = v.z; br[r4*4+3] = v.w;
    }
    #pragma unroll
    for (int q4 = 0; q4 < 4; q4++) {
        float4 o; float* op = &o.x;
        #pragma unroll
        for (int qq = 0; qq < 4; qq++) {
            int q = q4 * 4 + qq;
            float v = 0.f;
            #pragma unroll
            for (int r = 0; r < 16; r++) v += br[r] * C[r*16+q];
            op[qq] = v;
        }
        *(float4*)(g_D + (size_t)jrow * RNK + q4 * 4) = o;
    }
}

// ===================== kernel 4: T = x @ A^T (A staged in smem) =================
__global__ __launch_bounds__(256) void xat_kernel(
    const float* __restrict__ x, const float* __restrict__ A)
{
    __shared__ float As[16 * 512];          // 32 KB chunk of A
    const int tid  = threadIdx.x;
    const int lane = tid & 31;
    const int w    = tid >> 5;              // 8 warps, 2 rows each
    const int rbase = blockIdx.x * 16;

    float acc[2][16];
    #pragma unroll
    for (int a = 0; a < 2; a++)
        #pragma unroll
        for (int r = 0; r < 16; r++) acc[a][r] = 0.f;

    for (int kc = 0; kc < 8; kc++) {
        __syncthreads();
        #pragma unroll
        for (int i = 0; i < 8; i++) {
            int lin = tid + i * 256;          // float4 index, 2048 total
            int r = lin >> 7, c4 = lin & 127;
            ((float4*)As)[r * 128 + c4] =
                ((const float4*)(A + (size_t)r * INF + kc * 512))[c4];
        }
        __syncthreads();
        #pragma unroll
        for (int r2 = 0; r2 < 2; r2++) {
            int row = rbase + w * 2 + r2;
            const float4* xr = (const float4*)(x + (size_t)row * INF + kc * 512);
            #pragma unroll
            for (int i = 0; i < 4; i++) {
                int k4 = lane + i * 32;
                float4 xv = xr[k4];
                const float4* ac = ((const float4*)As) + k4;
                #pragma unroll
                for (int r = 0; r < 16; r++) {
                    float4 av = ac[r * 128];
                    acc[r2][r] += xv.x*av.x + xv.y*av.y + xv.z*av.z + xv.w*av.w;
                }
            }
        }
    }
    #pragma unroll
    for (int r2 = 0; r2 < 2; r2++) {
        #pragma unroll
        for (int r = 0; r < 16; r++) {
            #pragma unroll
            for (int off = 16; off > 0; off >>= 1)
                acc[r2][r] += __shfl_xor_sync(0xFFFFFFFFu, acc[r2][r], off);
        }
        if (lane < 16) {
            float outv = 0.f;
            #pragma unroll
            for (int r = 0; r < 16; r++) if (lane == r) outv = acc[r2][r];
            g_T[(size_t)(rbase + w * 2 + r2) * RNK + lane] = outv;
        }
    }
}

// ===================== kernel 5: tcgen05 GEMM (deep fine-grained pipeline) ======
#define KC 32
#define NITER (INF / KC)                 // 128
#define NSTG 6
#define TILE_B 8192                      // 128 rows x 64 B bf16 (SW64)
#define STAGE_B (4 * TILE_B)             // Ah, Al, Bh, Bl = 32 KB
#define SMEM_DYN (NSTG * STAGE_B + 1024 + 256)
// idesc: F32 accum, bf16 A/B K-major, M=256, N=256
#define MMA_IDESC ((1u << 4) | (1u << 7) | (1u << 10) | ((256u / 8) << 17) | ((256u / 16) << 24))

__global__ void __launch_bounds__(288, 1) __cluster_dims__(2, 1, 1)
gemm_tc_kernel(const float* __restrict__ x, const float* __restrict__ W,
               const float* __restrict__ bias, float* __restrict__ out)
{
    const int tid  = threadIdx.x;
    const uint32_t rank = cluster_ctarank();
    // supertile order: 64 clusters (8m x 8n) per supertile ~= one wave -> L2 reuse
    const int cid = blockIdx.x >> 1;
    const int st  = cid >> 6;            // 0..7  (4 m-supers x 2 n-supers)
    const int loc = cid & 63;
    const int m_tile = ((st >> 1) << 3) | (loc >> 3);   // 0..31
    const int n_tile = ((st & 1) << 3) | (loc & 7);     // 0..15
    const int m0 = m_tile * 256;
    const int n0 = n_tile * 256;

#if TC_PATH
    extern __shared__ char smem_raw[];
    const uint32_t raw = smem_to_u32(smem_raw);
    const uint32_t sb  = (raw + 1023u) & ~1023u;
    char* p_al = smem_raw + (sb - raw);

    const int wid  = tid >> 5;
    const int lane = tid & 31;

    const uint32_t ctrl    = sb + NSTG * STAGE_B;
    const uint32_t tmemptr = ctrl + 0;
    const uint32_t readyb  = ctrl + 8;    // 6 x 8B, count=2 (one arrive per CTA)
    const uint32_t freeb   = ctrl + 64;   // 6 x 8B, count=1 (tcgen05 commit)
    const uint32_t doneb   = ctrl + 120;  // count=1

    if (wid == 0) TCGEN05_ALLOC_CG2(tmemptr, 256);
    if (tid == 0) {
        #pragma unroll
        for (int s = 0; s < NSTG; s++) {
            MBARRIER_INIT(readyb + 8*s, 2);
            MBARRIER_INIT(freeb  + 8*s, 1);
        }
        MBARRIER_INIT(doneb, 1);
    }
    __syncthreads();
    uint32_t tmem_base;
    asm volatile("ld.shared.b32 %0, [%1];" : "=r"(tmem_base) : "r"(tmemptr));
    CLUSTER_SYNC();

    if (tid < 256) {
        // -------- producers: pure cp.async movers from precomputed bf16 ---------
        const char* srcs[4] = {
            (const char*)g_xhi + (size_t)(m0 + (int)rank * 128) * INF * 2,
            (const char*)g_xlo + (size_t)(m0 + (int)rank * 128) * INF * 2,
            (const char*)g_whi + (size_t)(n0 + (int)rank * 128) * INF * 2,
            (const char*)g_wlo + (size_t)(n0 + (int)rank * 128) * INF * 2
        };
        // stage tile: 128 rows x 64B (4 x 16B segs), SW64 swizzle: seg ^= (row>>1)&3
        uint32_t dstoff[2];
        size_t   srcoff[2];
        #pragma unroll
        for (int i = 0; i < 2; i++) {
            int cidx = tid + i * 256;          // 0..511 16B-chunks per tile
            int row = cidx >> 2, seg = cidx & 3;
            dstoff[i] = (uint32_t)row * 64 + (uint32_t)((seg ^ ((row >> 1) & 3)) << 4);
            srcoff[i] = (size_t)row * (INF * 2) + (size_t)seg * 16;
        }

        for (int it = 0; it < NITER; ++it) {
            const int s = it % NSTG;
            if (it >= NSTG)
                MBARRIER_WAIT_PARITY(freeb + 8*s, ((it / NSTG) - 1) & 1);
            const uint32_t stp = sb + (uint32_t)s * STAGE_B;
            const size_t kk2 = (size_t)it * (KC * 2);
            #pragma unroll
            for (int t4 = 0; t4 < 4; t4++) {
                const char* base = srcs[t4] + kk2;
                uint32_t tb = stp + (uint32_t)t4 * TILE_B;
                #pragma unroll
                for (int i = 0; i < 2; i++)
                    CP_ASYNC16(tb + dstoff[i], base + srcoff[i]);
            }
            CP_ASYNC_COMMIT();
            if (it >= 1) {
                // lagged readiness: only group (it-1) must be complete
                asm volatile("cp.async.wait_group 1;" ::: "memory");
                NAMED_BAR_PROD();
                if (tid == 0) {
                    FENCE_PROXY_ASYNC();
                    MBARRIER_ARRIVE_CLUSTER(readyb + 8 * ((it - 1) % NSTG), 0);
                }
            }
        }
        asm volatile("cp.async.wait_group 0;" ::: "memory");
        NAMED_BAR_PROD();
        if (tid == 0) {
            FENCE_PROXY_ASYNC();
            MBARRIER_ARRIVE_CLUSTER(readyb + 8 * ((NITER - 1) % NSTG), 0);
        }
    } else if (rank == 0 && wid == 8) {
        // -------- MMA issuer: one elected thread, never touches loads ----------
        if (elect_one_pred()) {
            bool first = true;
            for (int it = 0; it < NITER; ++it) {
                const int s = it % NSTG;
                MBARRIER_WAIT_PARITY_CLU(readyb + 8*s, (it / NSTG) & 1);
                const uint32_t stp = sb + (uint32_t)s * STAGE_B;
                uint64_t dAh = MAKE_SMEM_DESC64(stp + 0 * TILE_B);
                uint64_t dAl = MAKE_SMEM_DESC64(stp + 1 * TILE_B);
                uint64_t dBh = MAKE_SMEM_DESC64(stp + 2 * TILE_B);
                uint64_t dBl = MAKE_SMEM_DESC64(stp + 3 * TILE_B);
                #pragma unroll
                for (int k = 0; k < 2; k++) {
                    mma_f16_ss_cg2(tmem_base, dAh + k * 2, dBh + k * 2, MMA_IDESC, !first);
                    first = false;
                }
                #pragma unroll
                for (int k = 0; k < 2; k++)
                    mma_f16_ss_cg2(tmem_base, dAh + k * 2, dBl + k * 2, MMA_IDESC, true);
                #pragma unroll
                for (int k = 0; k < 2; k++)
                    mma_f16_ss_cg2(tmem_base, dAl + k * 2, dBh + k * 2, MMA_IDESC, true);
                if (it == NITER - 1) TCGEN05_COMMIT_MC_CG2(doneb, 0x3);
                else                 TCGEN05_COMMIT_MC_CG2(freeb + 8*s, 0x3);
            }
        }
    }

    // -------- all threads wait for final MMA, then fused epilogue ---------------
    MBARRIER_WAIT_PARITY(doneb, 0);
    TCGEN05_FENCE_AFTER();
    __syncthreads();

    float* ds_s   = (float*)p_al;              // [256][16] (reuses stage 0)
    float* bias_s = (float*)(p_al + 16384);    // [256]
    for (int i = tid; i < 1024; i += 288)
        ((float4*)ds_s)[i] = ((const float4*)(g_D + (size_t)n0 * RNK))[i];
    for (int i = tid; i < 64; i += 288)
        ((float4*)bias_s)[i] = ((const float4*)(bias + n0))[i];
    __syncthreads();

    if (wid < 8) {
        const int sub  = wid & 3;
        const int half = wid >> 2;
        const int m_glob = m0 + (int)rank * 128 + sub * 32 + lane;
        float t16[16];
        #pragma unroll
        for (int r4 = 0; r4 < 4; r4++) {
            float4 v = ((const float4*)(g_T + (size_t)m_glob * RNK))[r4];
            t16[r4*4+0] = v.x; t16[r4*4+1] = v.y; t16[r4*4+2] = v.z; t16[r4*4+3] = v.w;
        }
        float* orow = out + (size_t)m_glob * OUTF + n0;
        #pragma unroll 1
        for (int chunk = 0; chunk < 4; chunk++) {
            int col = half * 128 + chunk * 32;
            uint32_t dreg[32];
            TCGEN05_LD_32X32B_X32(dreg, tmem_base + (uint32_t)col);
            TCGEN05_WAIT_LD();
            #pragma unroll
            for (int j4 = 0; j4 < 8; j4++) {
                float4 o; float* op = &o.x;
                #pragma unroll
                for (int jj = 0; jj < 4; jj++) {
                    int j  = j4 * 4 + jj;
                    int nl = col + j;
                    float acc = __uint_as_float(dreg[j]) + bias_s[nl];
                    const float4* dv = (const float4*)(ds_s + nl * RNK);
                    #pragma unroll
                    for (int q4 = 0; q4 < 4; q4++) {
                        float4 d4 = dv[q4];
                        acc += t16[q4*4+0]*d4.x + t16[q4*4+1]*d4.y
                             + t16[q4*4+2]*d4.z + t16[q4*4+3]*d4.w;
                    }
                    op[jj] = acc;
                }
                *(float4*)(orow + col + j4 * 4) = o;
            }
        }
    }
    TCGEN05_FENCE_BEFORE();
    __syncthreads();
    if (wid == 0) {
        TCGEN05_RELINQ_CG2();
        TCGEN05_DEALLOC_CG2(tmem_base, 256);
    }
    CLUSTER_SYNC();
#else
    // Fallback for the non-arch-specific PTX pass (never selected on GB300).
    for (int idx = tid; idx < 128 * 256; idx += 288) {
        int mi = idx >> 8;
        int ni = idx & 255;
        int mg = m0 + (int)rank * 128 + mi;
        int ng = n0 + ni;
        const float* xr = x + (size_t)mg * INF;
        const float* wr = W + (size_t)ng * INF;
        float acc = bias[ng];
        for (int k = 0; k < INF; k++) acc += xr[k] * wr[k];
        for (int q = 0; q < RNK; q++) acc += g_T[(size_t)mg * RNK + q] * g_D[(size_t)ng * RNK + q];
        out[(size_t)mg * OUTF + ng] = acc;
    }
#endif
}

// ===================== launch ===================================================
extern "C" void kernel_launch(void* const* d_in, const int* in_sizes, int n_in,
                              void* d_out, int out_size) {
    const float* x      = (const float*)d_in[0];
    const float* W      = (const float*)d_in[1];
    const float* bias   = (const float*)d_in[2];
    const float* lora_A = (const float*)d_in[3];
    const float* lora_B = (const float*)d_in[4];
    float* out = (float*)d_out;

    cudaFuncSetAttribute(gemm_tc_kernel, cudaFuncAttributeMaxDynamicSharedMemorySize, SMEM_DYN);

    conv_kernel<<<2048, 256>>>(x, W);
    gram_kernel<<<512, 256>>>(lora_A, lora_B);
    ns_kernel<<<1, 256>>>();
    dmat_kernel<<<OUTF / 256, 256>>>(lora_B);
    xat_kernel<<<TOKENS / 16, 256>>>(x, lora_A);

    gemm_tc_kernel<<<1024, 288, SMEM_DYN>>>(x, W, bias, out);
}

// round 14
// speedup vs baseline: 1.3653x; 1.3653x over previous
#include <cuda_runtime.h>
#include <cuda_bf16.h>
#include <cstdint>

#define TOKENS 8192
#define INF    4096
#define OUTF   4096
#define RNK    16

// arch-specific (sm_103a) guard: tcgen05 only exists in the arch-specific pass.
#if defined(__CUDA_ARCH__) && (defined(__CUDA_ARCH_FEAT_SM103_ALL) || defined(__CUDA_ARCH_FEAT_SM100_ALL) || defined(__CUDA_ARCH_SPECIFIC__))
#define TC_PATH 1
#else
#define TC_PATH 0
#endif

// ===================== device scratch ==========================================
__device__ float g_KA[256];
__device__ float g_KB[256];
__device__ float g_C [256];
__device__ float g_T [TOKENS * RNK];
__device__ float g_D [OUTF   * RNK];
// bf16 hi/lo splits (4 bf16 packed per uint2)
__device__ uint2 g_xhi[(size_t)TOKENS * INF / 4];
__device__ uint2 g_xlo[(size_t)TOKENS * INF / 4];
__device__ uint2 g_whi[(size_t)OUTF   * INF / 4];
__device__ uint2 g_wlo[(size_t)OUTF   * INF / 4];

// ===================== portable PTX helpers ====================================
__device__ __forceinline__ uint32_t smem_to_u32(const void* p) {
    uint32_t a;
    asm("{ .reg .u64 t; cvta.to.shared.u64 t, %1; cvt.u32.u64 %0, t; }" : "=r"(a) : "l"(p));
    return a;
}
__device__ __forceinline__ uint32_t cluster_ctarank() {
    uint32_t r; asm("mov.u32 %0, %%cluster_ctarank;" : "=r"(r)); return r;
}
__device__ __forceinline__ uint32_t elect_one_pred() {
    uint32_t p;
    asm volatile("{\n\t.reg .pred p;\n\telect.sync _|p, 0xFFFFFFFF;\n\tselp.b32 %0, 1, 0, p;\n\t}" : "=r"(p));
    return p;
}

#define MBARRIER_INIT(addr, cnt) \
    asm volatile("mbarrier.init.shared.b64 [%0], %1;" :: "r"((uint32_t)(addr)), "r"((uint32_t)(cnt)) : "memory")

#define MBARRIER_ARRIVE_CLUSTER(addr, rank) \
    asm volatile("{\n\t.reg .b32 ra;\n\t" \
        "mapa.shared::cluster.u32 ra, %0, %1;\n\t" \
        "mbarrier.arrive.release.cluster.shared::cluster.b64 _, [ra];\n\t}" \
        :: "r"((uint32_t)(addr)), "r"((uint32_t)(rank)) : "memory")

#define MBARRIER_WAIT_PARITY(mbar, par) do { \
    uint32_t _m = (uint32_t)(mbar), _p = (uint32_t)(par), _d; \
    asm volatile("{\n\t.reg .pred p;\n\t" \
        "mbarrier.try_wait.parity.acquire.cta.shared::cta.b64 p, [%1], %2;\n\t" \
        "selp.b32 %0, 1, 0, p;\n\t}" : "=r"(_d) : "r"(_m), "r"(_p) : "memory"); \
    if (!_d) { \
        asm volatile("{\n\t.reg .pred P1;\n\t" \
            "WL_%=:\n\t" \
            "mbarrier.try_wait.parity.acquire.cta.shared::cta.b64 P1, [%0], %1, 0x989680;\n\t" \
            "@P1 bra.uni WD_%=;\n\t" \
            "bra.uni WL_%=;\n\t" \
            "WD_%=:\n\t}" :: "r"(_m), "r"(_p) : "memory"); \
    } \
} while (0)

#define MBARRIER_WAIT_PARITY_CLU(mbar, par) do { \
    uint32_t _m = (uint32_t)(mbar), _p = (uint32_t)(par), _d; \
    asm volatile("{\n\t.reg .pred p;\n\t" \
        "mbarrier.try_wait.parity.acquire.cluster.shared::cta.b64 p, [%1], %2;\n\t" \
        "selp.b32 %0, 1, 0, p;\n\t}" : "=r"(_d) : "r"(_m), "r"(_p) : "memory"); \
    if (!_d) { \
        asm volatile("{\n\t.reg .pred P1;\n\t" \
            "WLc_%=:\n\t" \
            "mbarrier.try_wait.parity.acquire.cluster.shared::cta.b64 P1, [%0], %1, 0x989680;\n\t" \
            "@P1 bra.uni WDc_%=;\n\t" \
            "bra.uni WLc_%=;\n\t" \
            "WDc_%=:\n\t}" :: "r"(_m), "r"(_p) : "memory"); \
    } \
} while (0)

#define CP_ASYNC16(dst, src) \
    asm volatile("cp.async.cg.shared.global [%0], [%1], 16;" :: "r"((uint32_t)(dst)), "l"(src) : "memory")
#define CP_ASYNC_COMMIT() asm volatile("cp.async.commit_group;" ::: "memory")
#define FENCE_PROXY_ASYNC() asm volatile("fence.proxy.async;" ::: "memory")
#define NAMED_BAR_PROD()    asm volatile("bar.sync 1, 256;" ::: "memory")
#define CLUSTER_SYNC() do { \
    asm volatile("barrier.cluster.arrive.aligned;" ::: "memory"); \
    asm volatile("barrier.cluster.wait.aligned;" ::: "memory"); \
} while (0)

// ===================== arch-specific tcgen05 helpers ===========================
#if TC_PATH
#define TCGEN05_ALLOC_CG2(sm, n) \
    asm volatile("tcgen05.alloc.cta_group::2.sync.aligned.shared::cta.b32 [%0], %1;" \
        :: "r"((uint32_t)(sm)), "r"((uint32_t)(n)) : "memory")
#define TCGEN05_DEALLOC_CG2(tm, n) \
    asm volatile("tcgen05.dealloc.cta_group::2.sync.aligned.b32 %0, %1;" :: "r"(tm), "r"((uint32_t)(n)))
#define TCGEN05_RELINQ_CG2() \
    asm volatile("tcgen05.relinquish_alloc_permit.cta_group::2.sync.aligned;")
#define TCGEN05_COMMIT_MC_CG2(mbar, mask) \
    asm volatile("tcgen05.commit.cta_group::2.mbarrier::arrive::one.shared::cluster.multicast::cluster.b64 [%0], %1;" \
        :: "r"((uint32_t)(mbar)), "h"((uint16_t)(mask)) : "memory")
#define TCGEN05_FENCE_AFTER()  asm volatile("tcgen05.fence::after_thread_sync;" ::: "memory")
#define TCGEN05_FENCE_BEFORE() asm volatile("tcgen05.fence::before_thread_sync;" ::: "memory")
#define TCGEN05_WAIT_LD()      asm volatile("tcgen05.wait::ld.sync.aligned;" ::: "memory")

#define TCGEN05_LD_32X32B_X32(r, a) \
    asm volatile("tcgen05.ld.sync.aligned.32x32b.x32.b32 " \
        "{%0, %1, %2, %3, %4, %5, %6, %7, %8, %9, %10, %11, %12, %13, %14, %15, " \
        "%16, %17, %18, %19, %20, %21, %22, %23, %24, %25, %26, %27, %28, %29, %30, %31}, [%32];" \
        : "=r"((r)[0]), "=r"((r)[1]), "=r"((r)[2]), "=r"((r)[3]), "=r"((r)[4]), "=r"((r)[5]), \
          "=r"((r)[6]), "=r"((r)[7]), "=r"((r)[8]), "=r"((r)[9]), "=r"((r)[10]), "=r"((r)[11]), \
          "=r"((r)[12]), "=r"((r)[13]), "=r"((r)[14]), "=r"((r)[15]), "=r"((r)[16]), "=r"((r)[17]), \
          "=r"((r)[18]), "=r"((r)[19]), "=r"((r)[20]), "=r"((r)[21]), "=r"((r)[22]), "=r"((r)[23]), \
          "=r"((r)[24]), "=r"((r)[25]), "=r"((r)[26]), "=r"((r)[27]), "=r"((r)[28]), "=r"((r)[29]), \
          "=r"((r)[30]), "=r"((r)[31]) : "r"(a))

__device__ __forceinline__ void mma_f16_ss_cg2(
    uint32_t d_tmem, uint64_t a_desc, uint64_t b_desc, uint32_t idesc, bool en_d)
{
    uint32_t en = en_d ? 1 : 0;
    asm volatile(
        "{\n\t.reg .pred p;\n\t"
        "setp.ne.u32 p, %6, 0;\n\t"
        "tcgen05.mma.cta_group::2.kind::f16 [%0], %1, %2, %3, "
        "{%4, %4, %4, %4, %4, %4, %4, %4}, p;\n\t}"
        :: "r"(d_tmem), "l"(a_desc), "l"(b_desc), "r"(idesc),
           "r"(0u), "r"(0u), "r"(en)
        : "memory");
}
#endif // TC_PATH

static constexpr uint64_t SMEM_DESC_BASE_SW128 =
    (uint64_t(2) << 61) | (uint64_t(1) << 46) | (uint64_t(64) << 32) | (uint64_t(1) << 16);
#define MAKE_SMEM_DESC(a) (SMEM_DESC_BASE_SW128 | ((uint64_t)((a) >> 4) & 0x3FFF))

// ===================== kernel 0: f32 -> bf16 hi/lo split (once) =================
__global__ void conv_kernel(const float* __restrict__ x, const float* __restrict__ W) {
    const int64_t NX4 = (int64_t)TOKENS * INF / 4;
    const int64_t NW4 = (int64_t)OUTF   * INF / 4;
    const int64_t total = NX4 + NW4;
    int64_t stride = (int64_t)gridDim.x * blockDim.x;
    for (int64_t i = (int64_t)blockIdx.x * blockDim.x + threadIdx.x; i < total; i += stride) {
        float4 v = (i < NX4) ? ((const float4*)x)[i] : ((const float4*)W)[i - NX4];
        __nv_bfloat162 h0 = __floats2bfloat162_rn(v.x, v.y);
        __nv_bfloat162 h1 = __floats2bfloat162_rn(v.z, v.w);
        float2 f0 = __bfloat1622float2(h0);
        float2 f1 = __bfloat1622float2(h1);
        __nv_bfloat162 l0 = __floats2bfloat162_rn(v.x - f0.x, v.y - f0.y);
        __nv_bfloat162 l1 = __floats2bfloat162_rn(v.z - f1.x, v.w - f1.y);
        union U { __nv_bfloat162 b; unsigned u; };
        U ch0{h0}, ch1{h1}, cl0{l0}, cl1{l1};
        uint2 hv = make_uint2(ch0.u, ch1.u);
        uint2 lv = make_uint2(cl0.u, cl1.u);
        if (i < NX4) { g_xhi[i] = hv; g_xlo[i] = lv; }
        else         { g_whi[i - NX4] = hv; g_wlo[i - NX4] = lv; }
    }
}

// ===================== kernel 1: gram matrices ==================================
__global__ void gram_kernel(const float* __restrict__ A, const float* __restrict__ B) {
    __shared__ float red[256];
    int t = threadIdx.x, b = blockIdx.x;
    float s = 0.f;
    if (b < 256) {
        int i = b >> 4, j = b & 15;
        const float* ai = A + (size_t)i * INF;
        const float* aj = A + (size_t)j * INF;
        for (int k = t; k < INF; k += 256) s += ai[k] * aj[k];
    } else {
        int bb = b - 256;
        int i = bb >> 4, j = bb & 15;
        for (int k = t; k < OUTF; k += 256) s += B[(size_t)k * RNK + i] * B[(size_t)k * RNK + j];
    }
    red[t] = s; __syncthreads();
    for (int o = 128; o > 0; o >>= 1) { if (t < o) red[t] += red[t + o]; __syncthreads(); }
    if (t == 0) { if (b < 256) g_KA[b] = red[0]; else g_KB[b - 256] = red[0]; }
}

// ===================== kernel 2: Newton-Schulz (rank-16 subspace) ===============
__global__ void ns_kernel() {
    __shared__ float KA[256], KB[256], M[256], Y[256], Z[256], T1[256], T2[256];
    int t = threadIdx.x, i = t >> 4, j = t & 15;
    KA[t] = g_KA[t]; KB[t] = g_KB[t];
    __syncthreads();
    T1[t] = KA[t] * KB[t];
    __syncthreads();
    for (int o = 128; o > 0; o >>= 1) { if (t < o) T1[t] += T1[t + o]; __syncthreads(); }
    float alpha = sqrtf(T1[0]);
    __syncthreads();
    float s = alpha + 1e-7f;
    M[t] = (i == j) ? (1.0f / s) : 0.0f;
    __syncthreads();
    const float ca = 3.4445f, cb = -4.775f, cc = 2.0315f;
    #pragma unroll 1
    for (int it = 0; it < 5; it++) {
        float v = 0.f;
        #pragma unroll
        for (int q = 0; q < 16; q++) v += M[i*16+q] * KA[q*16+j];
        T1[t] = v; __syncthreads();
        v = 0.f;
        #pragma unroll
        for (int q = 0; q < 16; q++) v += T1[i*16+q] * M[j*16+q];
        Y[t] = v; __syncthreads();
        v = 0.f;
        #pragma unroll
        for (int q = 0; q < 16; q++) v += Y[i*16+q] * KB[q*16+j];
        T2[t] = v; __syncthreads();
        v = 0.f;
        #pragma unroll
        for (int q = 0; q < 16; q++) v += T2[i*16+q] * Y[q*16+j];
        Z[t] = v; __syncthreads();
        Y[t] = cb * Y[t] + cc * Z[t]; __syncthreads();
        v = 0.f;
        #pragma unroll
        for (int q = 0; q < 16; q++) v += Y[i*16+q] * KB[q*16+j];
        T2[t] = v; __syncthreads();
        v = ca * M[t];
        #pragma unroll
        for (int q = 0; q < 16; q++) v += T2[i*16+q] * M[q*16+j];
        T1[t] = v; __syncthreads();
        M[t] = T1[t]; __syncthreads();
    }
    g_C[t] = alpha * M[t];
}

// ===================== kernel 3: D = B @ (alpha*Mf) =============================
__global__ void dmat_kernel(const float* __restrict__ B) {
    __shared__ float C[256];
    int t = threadIdx.x;
    C[t] = g_C[t];
    __syncthreads();
    int jrow = blockIdx.x * 256 + t;
    float br[16];
    #pragma unroll
    for (int r4 = 0; r4 < 4; r4++) {
        float4 v = *(const float4*)(B + (size_t)jrow * RNK + r4 * 4);
        br[r4*4+0] = v.x; br[r4*4+1] = v.y; br[r4*4+2] = v.z; br[r4*4+3] = v.w;
    }
    #pragma unroll
    for (int q4 = 0; q4 < 4; q4++) {
        float4 o; float* op = &o.x;
        #pragma unroll
        for (int qq = 0; qq < 4; qq++) {
            int q = q4 * 4 + qq;
            float v = 0.f;
            #pragma unroll
            for (int r = 0; r < 16; r++) v += br[r] * C[r*16+q];
            op[qq] = v;
        }
        *(float4*)(g_D + (size_t)jrow * RNK + q4 * 4) = o;
    }
}

// ===================== kernel 4: T = x @ A^T (A staged in smem) =================
__global__ __launch_bounds__(256) void xat_kernel(
    const float* __restrict__ x, const float* __restrict__ A)
{
    __shared__ float As[16 * 512];          // 32 KB chunk of A
    const int tid  = threadIdx.x;
    const int lane = tid & 31;
    const int w    = tid >> 5;              // 8 warps, 2 rows each
    const int rbase = blockIdx.x * 16;

    float acc[2][16];
    #pragma unroll
    for (int a = 0; a < 2; a++)
        #pragma unroll
        for (int r = 0; r < 16; r++) acc[a][r] = 0.f;

    for (int kc = 0; kc < 8; kc++) {
        __syncthreads();
        #pragma unroll
        for (int i = 0; i < 8; i++) {
            int lin = tid + i * 256;          // float4 index, 2048 total
            int r = lin >> 7, c4 = lin & 127;
            ((float4*)As)[r * 128 + c4] =
                ((const float4*)(A + (size_t)r * INF + kc * 512))[c4];
        }
        __syncthreads();
        #pragma unroll
        for (int r2 = 0; r2 < 2; r2++) {
            int row = rbase + w * 2 + r2;
            const float4* xr = (const float4*)(x + (size_t)row * INF + kc * 512);
            #pragma unroll
            for (int i = 0; i < 4; i++) {
                int k4 = lane + i * 32;
                float4 xv = xr[k4];
                const float4* ac = ((const float4*)As) + k4;
                #pragma unroll
                for (int r = 0; r < 16; r++) {
                    float4 av = ac[r * 128];
                    acc[r2][r] += xv.x*av.x + xv.y*av.y + xv.z*av.z + xv.w*av.w;
                }
            }
        }
    }
    #pragma unroll
    for (int r2 = 0; r2 < 2; r2++) {
        #pragma unroll
        for (int r = 0; r < 16; r++) {
            #pragma unroll
            for (int off = 16; off > 0; off >>= 1)
                acc[r2][r] += __shfl_xor_sync(0xFFFFFFFFu, acc[r2][r], off);
        }
        if (lane < 16) {
            float outv = 0.f;
            #pragma unroll
            for (int r = 0; r < 16; r++) if (lane == r) outv = acc[r2][r];
            g_T[(size_t)(rbase + w * 2 + r2) * RNK + lane] = outv;
        }
    }
}

// ===================== kernel 5: tcgen05 GEMM (dual-accumulator, 256x512) =======
#define KC 64
#define NITER (INF / KC)                 // 64
#define NSTG 2
#define TILE_B 16384                     // 128 rows x 128 B bf16 (SW128)
#define NTILES 6                         // Ah, Al, Bh, Bl, B2h, B2l
#define STAGE_B (NTILES * TILE_B)        // 96 KB
#define SMEM_DYN (NSTG * STAGE_B + 1024 + 256)
// idesc: F32 accum, bf16 A/B K-major, M=256, N=256
#define MMA_IDESC ((1u << 4) | (1u << 7) | (1u << 10) | ((256u / 8) << 17) | ((256u / 16) << 24))

__global__ void __launch_bounds__(288, 1) __cluster_dims__(2, 1, 1)
gemm_tc_kernel(const float* __restrict__ x, const float* __restrict__ W,
               const float* __restrict__ bias, float* __restrict__ out)
{
    const int tid  = threadIdx.x;
    const uint32_t rank = cluster_ctarank();
    // 256 clusters: 32 m-tiles x 8 n-pairs. supertile = 8m x 8np (~one wave).
    const int cid = blockIdx.x >> 1;            // 0..255
    const int st  = cid >> 6;                   // 0..3 (m-super)
    const int loc = cid & 63;
    const int m_tile = (st << 3) | (loc >> 3);  // 0..31
    const int np     = loc & 7;                 // 0..7
    const int m0 = m_tile * 256;
    const int n0 = np * 512;

#if TC_PATH
    extern __shared__ char smem_raw[];
    const uint32_t raw = smem_to_u32(smem_raw);
    const uint32_t sb  = (raw + 1023u) & ~1023u;
    char* p_al = smem_raw + (sb - raw);

    const int wid  = tid >> 5;
    const int lane = tid & 31;

    const uint32_t ctrl    = sb + NSTG * STAGE_B;
    const uint32_t tmemptr = ctrl + 0;
    const uint32_t readyb  = ctrl + 8;    // 2 x 8B, count=2 (one arrive per CTA)
    const uint32_t freeb   = ctrl + 24;   // 2 x 8B, count=1 (tcgen05 commit)
    const uint32_t doneb   = ctrl + 40;   // count=1

    if (wid == 0) TCGEN05_ALLOC_CG2(tmemptr, 512);
    if (tid == 0) {
        #pragma unroll
        for (int s = 0; s < NSTG; s++) {
            MBARRIER_INIT(readyb + 8*s, 2);
            MBARRIER_INIT(freeb  + 8*s, 1);
        }
        MBARRIER_INIT(doneb, 1);
    }
    __syncthreads();
    uint32_t tmem_base;
    asm volatile("ld.shared.b32 %0, [%1];" : "=r"(tmem_base) : "r"(tmemptr));
    CLUSTER_SYNC();

    if (tid < 256) {
        // -------- producers: pure cp.async movers (6 tiles/stage) ---------------
        const char* srcs[NTILES] = {
            (const char*)g_xhi + (size_t)(m0 + (int)rank * 128) * INF * 2,
            (const char*)g_xlo + (size_t)(m0 + (int)rank * 128) * INF * 2,
            (const char*)g_whi + (size_t)(n0 + (int)rank * 128) * INF * 2,
            (const char*)g_wlo + (size_t)(n0 + (int)rank * 128) * INF * 2,
            (const char*)g_whi + (size_t)(n0 + 256 + (int)rank * 128) * INF * 2,
            (const char*)g_wlo + (size_t)(n0 + 256 + (int)rank * 128) * INF * 2
        };
        uint32_t dstoff[4];
        size_t   srcoff[4];
        #pragma unroll
        for (int i = 0; i < 4; i++) {
            int sid = tid + i * 256;          // 0..1023 16B-chunks per tile
            int row = sid >> 3, seg = sid & 7;
            dstoff[i] = (uint32_t)row * 128 + (uint32_t)((seg ^ (row & 7)) << 4);
            srcoff[i] = (size_t)row * (INF * 2) + (size_t)seg * 16;
        }

        for (int it = 0; it < NITER; ++it) {
            const int s = it & 1;
            if (it >= NSTG)
                MBARRIER_WAIT_PARITY(freeb + 8*s, ((it >> 1) - 1) & 1);
            const uint32_t stp = sb + (uint32_t)s * STAGE_B;
            const size_t kk2 = (size_t)it * (KC * 2);
            #pragma unroll
            for (int t6 = 0; t6 < NTILES; t6++) {
                const char* base = srcs[t6] + kk2;
                uint32_t tb = stp + (uint32_t)t6 * TILE_B;
                #pragma unroll
                for (int i = 0; i < 4; i++)
                    CP_ASYNC16(tb + dstoff[i], base + srcoff[i]);
            }
            CP_ASYNC_COMMIT();
            asm volatile("cp.async.wait_group 0;" ::: "memory");
            NAMED_BAR_PROD();
            if (tid == 0) {
                FENCE_PROXY_ASYNC();
                MBARRIER_ARRIVE_CLUSTER(readyb + 8*s, 0);
            }
        }
    } else if (rank == 0 && wid == 8) {
        // -------- MMA issuer: 24 dispatches/stage into two accumulators --------
        if (elect_one_pred()) {
            bool first0 = true, first1 = true;
            const uint32_t acc0 = tmem_base;
            const uint32_t acc1 = tmem_base + 256;
            for (int it = 0; it < NITER; ++it) {
                const int s = it & 1;
                MBARRIER_WAIT_PARITY_CLU(readyb + 8*s, (it >> 1) & 1);
                const uint32_t stp = sb + (uint32_t)s * STAGE_B;
                uint64_t dAh  = MAKE_SMEM_DESC(stp + 0 * TILE_B);
                uint64_t dAl  = MAKE_SMEM_DESC(stp + 1 * TILE_B);
                uint64_t dBh  = MAKE_SMEM_DESC(stp + 2 * TILE_B);
                uint64_t dBl  = MAKE_SMEM_DESC(stp + 3 * TILE_B);
                uint64_t dB2h = MAKE_SMEM_DESC(stp + 4 * TILE_B);
                uint64_t dB2l = MAKE_SMEM_DESC(stp + 5 * TILE_B);
                #pragma unroll
                for (int k = 0; k < 4; k++) {
                    mma_f16_ss_cg2(acc0, dAh + k * 2, dBh + k * 2, MMA_IDESC, !first0);
                    first0 = false;
                }
                #pragma unroll
                for (int k = 0; k < 4; k++)
                    mma_f16_ss_cg2(acc0, dAh + k * 2, dBl + k * 2, MMA_IDESC, true);
                #pragma unroll
                for (int k = 0; k < 4; k++)
                    mma_f16_ss_cg2(acc0, dAl + k * 2, dBh + k * 2, MMA_IDESC, true);
                #pragma unroll
                for (int k = 0; k < 4; k++) {
                    mma_f16_ss_cg2(acc1, dAh + k * 2, dB2h + k * 2, MMA_IDESC, !first1);
                    first1 = false;
                }
                #pragma unroll
                for (int k = 0; k < 4; k++)
                    mma_f16_ss_cg2(acc1, dAh + k * 2, dB2l + k * 2, MMA_IDESC, true);
                #pragma unroll
                for (int k = 0; k < 4; k++)
                    mma_f16_ss_cg2(acc1, dAl + k * 2, dB2h + k * 2, MMA_IDESC, true);
                if (it == NITER - 1) TCGEN05_COMMIT_MC_CG2(doneb, 0x3);
                else                 TCGEN05_COMMIT_MC_CG2(freeb + 8*s, 0x3);
            }
        }
    }

    // -------- all threads wait for final MMA, then fused epilogue ---------------
    MBARRIER_WAIT_PARITY(doneb, 0);
    TCGEN05_FENCE_AFTER();
    __syncthreads();

    float* ds_s   = (float*)p_al;              // [512][16] (reuses stage area)
    float* bias_s = (float*)(p_al + 32768);    // [512]
    for (int i = tid; i < 2048; i += 288)
        ((float4*)ds_s)[i] = ((const float4*)(g_D + (size_t)n0 * RNK))[i];
    for (int i = tid; i < 128; i += 288)
        ((float4*)bias_s)[i] = ((const float4*)(bias + n0))[i];
    __syncthreads();

    if (wid < 8) {
        const int sub  = wid & 3;
        const int half = wid >> 2;
        const int m_glob = m0 + (int)rank * 128 + sub * 32 + lane;
        float t16[16];
        #pragma unroll
        for (int r4 = 0; r4 < 4; r4++) {
            float4 v = ((const float4*)(g_T + (size_t)m_glob * RNK))[r4];
            t16[r4*4+0] = v.x; t16[r4*4+1] = v.y; t16[r4*4+2] = v.z; t16[r4*4+3] = v.w;
        }
        float* orow = out + (size_t)m_glob * OUTF + n0;
        #pragma unroll 1
        for (int chunk = 0; chunk < 8; chunk++) {
            // col_local 0..511: acc = chunk>>2, within-acc col = half*128 + (chunk&3)*32
            int col = (chunk >> 2) * 256 + half * 128 + (chunk & 3) * 32;
            uint32_t dreg[32];
            TCGEN05_LD_32X32B_X32(dreg, tmem_base + (uint32_t)col);
            TCGEN05_WAIT_LD();
            #pragma unroll
            for (int j4 = 0; j4 < 8; j4++) {
                float4 o; float* op = &o.x;
                #pragma unroll
                for (int jj = 0; jj < 4; jj++) {
                    int j  = j4 * 4 + jj;
                    int nl = col + j;
                    float acc = __uint_as_float(dreg[j]) + bias_s[nl];
                    const float4* dv = (const float4*)(ds_s + nl * RNK);
                    #pragma unroll
                    for (int q4 = 0; q4 < 4; q4++) {
                        float4 d4 = dv[q4];
                        acc += t16[q4*4+0]*d4.x + t16[q4*4+1]*d4.y
                             + t16[q4*4+2]*d4.z + t16[q4*4+3]*d4.w;
                    }
                    op[jj] = acc;
                }
                *(float4*)(orow + col + j4 * 4) = o;
            }
        }
    }
    TCGEN05_FENCE_BEFORE();
    __syncthreads();
    if (wid == 0) {
        TCGEN05_RELINQ_CG2();
        TCGEN05_DEALLOC_CG2(tmem_base, 512);
    }
    CLUSTER_SYNC();
#else
    // Fallback for the non-arch-specific PTX pass (never selected on GB300).
    for (int idx = tid; idx < 128 * 512; idx += 288) {
        int mi = idx >> 9;
        int ni = idx & 511;
        int mg = m0 + (int)rank * 128 + mi;
        int ng = n0 + ni;
        const float* xr = x + (size_t)mg * INF;
        const float* wr = W + (size_t)ng * INF;
        float acc = bias[ng];
        for (int k = 0; k < INF; k++) acc += xr[k] * wr[k];
        for (int q = 0; q < RNK; q++) acc += g_T[(size_t)mg * RNK + q] * g_D[(size_t)ng * RNK + q];
        out[(size_t)mg * OUTF + ng] = acc;
    }
#endif
}

// ===================== launch ===================================================
extern "C" void kernel_launch(void* const* d_in, const int* in_sizes, int n_in,
                              void* d_out, int out_size) {
    const float* x      = (const float*)d_in[0];
    const float* W      = (const float*)d_in[1];
    const float* bias   = (const float*)d_in[2];
    const float* lora_A = (const float*)d_in[3];
    const float* lora_B = (const float*)d_in[4];
    float* out = (float*)d_out;

    cudaFuncSetAttribute(gemm_tc_kernel, cudaFuncAttributeMaxDynamicSharedMemorySize, SMEM_DYN);

    conv_kernel<<<2048, 256>>>(x, W);
    gram_kernel<<<512, 256>>>(lora_A, lora_B);
    ns_kernel<<<1, 256>>>();
    dmat_kernel<<<OUTF / 256, 256>>>(lora_B);
    xat_kernel<<<TOKENS / 16, 256>>>(x, lora_A);

    gemm_tc_kernel<<<512, 288, SMEM_DYN>>>(x, W, bias, out);
}